// round 4
// baseline (speedup 1.0000x reference)
#include <cuda_runtime.h>

#define THREADS 256
#define TB 16
// smem: wp [m][n][4] 64KB + wm 64KB + 2 x-buffers of 32KB = 192KB
#define SMEM_BYTES 196608

typedef unsigned long long ull;

__device__ __forceinline__ ull pk2(float lo, float hi) {
    ull r;
    asm("mov.b64 %0, {%1, %2};" : "=l"(r) : "f"(lo), "f"(hi));
    return r;
}
__device__ __forceinline__ void unpk(ull v, float& lo, float& hi) {
    asm("mov.b64 {%0, %1}, %2;" : "=f"(lo), "=f"(hi) : "l"(v));
}
__device__ __forceinline__ ull ffma2(ull a, ull b, ull c) {
    ull d;
    asm("fma.rn.f32x2 %0, %1, %2, %3;" : "=l"(d) : "l"(a), "l"(b), "l"(c));
    return d;
}

// stage one tile (TB batches = TB*64*8 floats = 32KB, contiguous) into smem
__device__ __forceinline__ void stage_tile(const float* __restrict__ x,
                                           float* dst, int tile, int tid) {
    const float4* src = reinterpret_cast<const float4*>(x) + (size_t)tile * (TB * 128);
    float4* d4 = reinterpret_cast<float4*>(dst);
#pragma unroll
    for (int k = 0; k < 8; k++) {
        int i = tid + k * THREADS;
        unsigned int ds = (unsigned int)__cvta_generic_to_shared(d4 + i);
        asm volatile("cp.async.cg.shared.global [%0], [%1], 16;\n"
                     :: "r"(ds), "l"(src + i));
    }
    asm volatile("cp.async.commit_group;\n");
}

__global__ __launch_bounds__(THREADS, 1)
void clifford_gate_kernel(const float* __restrict__ x,
                          const float* __restrict__ wp,
                          const float* __restrict__ bpr,
                          const float* __restrict__ wm,
                          const float* __restrict__ bmr,
                          float* __restrict__ out,
                          int ntiles) {
    extern __shared__ float smf[];
    float4* wsp = reinterpret_cast<float4*>(smf);          // 4096 float4, [m*64+n]
    float4* wsm = wsp + 4096;                               // 4096 float4
    float*  xb  = smf + 32768;                              // 2 * 8192 floats

    const int tid  = threadIdx.x;
    const int lane = tid & 31;
    const int warp = tid >> 5;
    const int n    = ((warp & 1) << 5) | lane;   // 0..63
    const int bg4  = (warp >> 1) << 2;           // local b base: 0,4,8,12

    // ---- stage weights once: gmem [n][m][4] -> smem [m][n][4] ----
    {
        const float4* gp = reinterpret_cast<const float4*>(wp);
        const float4* gm = reinterpret_cast<const float4*>(wm);
        for (int idx = tid; idx < 4096; idx += THREADS) {
            int nn = idx & 63, mm = idx >> 6;
            wsp[mm * 64 + nn] = gp[nn * 64 + mm];
            wsm[mm * 64 + nn] = gm[nn * 64 + mm];
        }
    }
    const float biasp = bpr[n];
    const float biasm = bmr[n];

    int t = blockIdx.x;
    const int stride = gridDim.x;
    if (t < ntiles) stage_tile(x, xb, t, tid);
    asm volatile("cp.async.wait_group 0;\n");
    __syncthreads();

    int cur = 0;
    const float s2 = 0.70710678118654752440f;

    for (; t < ntiles; t += stride) {
        int tn = t + stride;
        if (tn < ntiles) stage_tile(x, xb + (cur ^ 1) * 8192, tn, tid);

        // ---------------- mainloop: packed f32x2 GEMM ----------------
        // Reduction order: single accumulator per output element, m ascending,
        // fused fma each step (acc starts at 0 so step 0 == rounded product).
        // This is bit-identical to Eigen gebp / cublas sgemm per-element loops.
        ull aP[4][4], aM[4][4];
#pragma unroll
        for (int i = 0; i < 4; i++)
#pragma unroll
            for (int j = 0; j < 4; j++) { aP[i][j] = 0ull; aM[i][j] = 0ull; }

        const float* xbc = xb + cur * 8192;
#pragma unroll 4
        for (int m = 0; m < 64; m++) {
            float4 wpv = wsp[m * 64 + n];
            float4 wmv = wsm[m * 64 + n];
            // SUBSPACE pairs: (c0,c1)->(w0,w1) (c2,c3)->(w1,w1)
            //                 (c4,c5)->(w2,w2) (c6,c7)->(w2,w3)
            ull wpA = pk2(wpv.x, wpv.y), wpB = pk2(wpv.y, wpv.y);
            ull wpC = pk2(wpv.z, wpv.z), wpD = pk2(wpv.z, wpv.w);
            ull wmA = pk2(wmv.x, wmv.y), wmB = pk2(wmv.y, wmv.y);
            ull wmC = pk2(wmv.z, wmv.z), wmD = pk2(wmv.z, wmv.w);
#pragma unroll
            for (int bb = 0; bb < 4; bb++) {
                const ulonglong2* xp = reinterpret_cast<const ulonglong2*>(
                    xbc + (((bg4 + bb) << 6) + m) * 8);
                ulonglong2 x01 = xp[0];
                ulonglong2 x23 = xp[1];
                aP[bb][0] = ffma2(x01.x, wpA, aP[bb][0]);
                aP[bb][1] = ffma2(x01.y, wpB, aP[bb][1]);
                aP[bb][2] = ffma2(x23.x, wpC, aP[bb][2]);
                aP[bb][3] = ffma2(x23.y, wpD, aP[bb][3]);
                aM[bb][0] = ffma2(x01.x, wmA, aM[bb][0]);
                aM[bb][1] = ffma2(x01.y, wmB, aM[bb][1]);
                aM[bb][2] = ffma2(x23.x, wmC, aM[bb][2]);
                aM[bb][3] = ffma2(x23.y, wmD, aM[bb][3]);
            }
        }

        // ---------------- epilogue ----------------
        size_t bbase = (size_t)t * TB + bg4;
#pragma unroll
        for (int bb = 0; bb < 4; bb++) {
            float p0, p1, p2, p3, p4, p5, p6, p7;
            float m0, m1, m2, m3, m4, m5, m6, m7;
            unpk(aP[bb][0], p0, p1); unpk(aP[bb][1], p2, p3);
            unpk(aP[bb][2], p4, p5); unpk(aP[bb][3], p6, p7);
            unpk(aM[bb][0], m0, m1); unpk(aM[bb][1], m2, m3);
            unpk(aM[bb][2], m4, m5); unpk(aM[bb][3], m6, m7);
            // bias: one explicit rounded add (reference: y.at[...,0].add(bias))
            p0 = __fadd_rn(p0, biasp);
            m0 = __fadd_rn(m0, biasm);

            // gate b = sum_i (p_i*BETA_i*BILINEAR_i)*m_i ; BETA*BILINEAR = +1.
            // XLA: individually ROUNDED multiplies, then sequential add i=0..7.
            // No FMA fusion allowed here — catastrophic near b==0.
            float bgv;
            bgv = __fmul_rn(p0, m0);
            bgv = __fadd_rn(bgv, __fmul_rn(p1, m1));
            bgv = __fadd_rn(bgv, __fmul_rn(p2, m2));
            bgv = __fadd_rn(bgv, __fmul_rn(p3, m3));
            bgv = __fadd_rn(bgv, __fmul_rn(p4, m4));
            bgv = __fadd_rn(bgv, __fmul_rn(p5, m5));
            bgv = __fadd_rn(bgv, __fmul_rn(p6, m6));
            bgv = __fadd_rn(bgv, __fmul_rn(p7, m7));

            // q = m0^2+..+m3^2 - m4^2-..-m7^2, same rounding discipline.
            // Signs (±1 factors) are exact; squares rounded once each;
            // strict sequential accumulation i=0..7.
            float q;
            q = __fmul_rn(m0, m0);
            q = __fadd_rn(q, __fmul_rn(m1, m1));
            q = __fadd_rn(q, __fmul_rn(m2, m2));
            q = __fadd_rn(q, __fmul_rn(m3, m3));
            q = __fadd_rn(q, -__fmul_rn(m4, m4));
            q = __fadd_rn(q, -__fmul_rn(m5, m5));
            q = __fadd_rn(q, -__fmul_rn(m6, m6));
            q = __fadd_rn(q, -__fmul_rn(m7, m7));

            // norm = (q^2 + 1e-16)^(1/4); well-conditioned given q, so ulp
            // differences in the root/reciprocal are harmless.
            float qs  = __fadd_rn(__fmul_rn(q, q), 1e-16f);
            float nrm = __fsqrt_rn(__fsqrt_rn(qs));
            float inv = __frcp_rn(nrm);

            float n0 = m0 * inv, n1 = m1 * inv, n2 = m2 * inv, n3 = m3 * inv;
            float n4 = m4 * inv, n5 = m5 * inv, n6 = m6 * inv, n7 = m7 * inv;

            // Cl(3,0) geometric product r = p * n  (well-conditioned; fma ok)
            float r0 = p0*n0 + p1*n1 + p2*n2 + p3*n3 - p4*n4 - p5*n5 - p6*n6 - p7*n7;
            float r1 = p0*n1 + p1*n0 - p2*n4 + p4*n2 - p3*n5 + p5*n3 - p6*n7 - p7*n6;
            float r2 = p0*n2 + p2*n0 + p1*n4 - p4*n1 - p3*n6 + p6*n3 + p5*n7 + p7*n5;
            float r3 = p0*n3 + p3*n0 + p1*n5 - p5*n1 + p2*n6 - p6*n2 - p4*n7 - p7*n4;
            float r4 = p0*n4 + p4*n0 + p1*n2 - p2*n1 + p3*n7 + p7*n3 - p5*n6 + p6*n5;
            float r5 = p0*n5 + p5*n0 + p1*n3 - p3*n1 - p2*n7 - p7*n2 + p4*n6 - p6*n4;
            float r6 = p0*n6 + p6*n0 + p1*n7 + p7*n1 + p2*n3 - p3*n2 - p4*n5 + p5*n4;
            float r7 = p0*n7 + p7*n0 + p1*n6 + p6*n1 - p2*n5 - p5*n2 + p3*n4 + p4*n3;

            bool sel = bgv > 0.0f;
            float4 o0, o1;
            o0.x = (sel ? p0 : r0) * s2;
            o0.y = (sel ? p1 : r1) * s2;
            o0.z = (sel ? p2 : r2) * s2;
            o0.w = (sel ? p3 : r3) * s2;
            o1.x = (sel ? p4 : r4) * s2;
            o1.y = (sel ? p5 : r5) * s2;
            o1.z = (sel ? p6 : r6) * s2;
            o1.w = (sel ? p7 : r7) * s2;

            size_t brow = bbase + bb;
            float4* op = reinterpret_cast<float4*>(out + ((brow << 6) + n) * 8);
            op[0] = o0;
            op[1] = o1;
        }

        asm volatile("cp.async.wait_group 0;\n");
        __syncthreads();
        cur ^= 1;
    }
}

extern "C" void kernel_launch(void* const* d_in, const int* in_sizes, int n_in,
                              void* d_out, int out_size) {
    const float* x   = (const float*)d_in[0];
    const float* wp  = (const float*)d_in[1];
    const float* bpr = (const float*)d_in[2];
    const float* wm  = (const float*)d_in[3];
    const float* bmr = (const float*)d_in[4];
    float* out = (float*)d_out;

    int B = in_sizes[0] / 512;      // x is (B, 64, 8)
    int ntiles = B / TB;

    cudaFuncSetAttribute(clifford_gate_kernel,
                         cudaFuncAttributeMaxDynamicSharedMemorySize, SMEM_BYTES);

    int dev = 0, sms = 148;
    cudaGetDevice(&dev);
    cudaDeviceGetAttribute(&sms, cudaDevAttrMultiProcessorCount, dev);
    int grid = sms < ntiles ? sms : ntiles;
    if (grid < 1) grid = 1;

    clifford_gate_kernel<<<grid, THREADS, SMEM_BYTES>>>(
        x, wp, bpr, wm, bmr, out, ntiles);
}